// round 1
// baseline (speedup 1.0000x reference)
#include <cuda_runtime.h>
#include <cuda_bf16.h>

// TALayer: equivalent 9-tap 1D conv, tap offsets d_j = 16*(j/3) + (j%3) - 17
//   => {-17,-16,-15, -1,0,+1, +15,+16,+17}, zero-padded at sequence edges.
// out[b,o,t] = bias[o] + sum_c sum_j W[o,c,j] * x[b,c,t+d_j]

#define NC 64
#define NO 64
#define KT 9
#define T_TILE 256
#define HALO 17
#define XT (T_TILE + 2 * HALO)   // 290
#define XSTRIDE XT               // smem row stride (floats)

// Pre-transposed weights: g_wt[(c*9 + j)*64 + o]
__device__ float g_wt[NC * KT * NO];

__global__ void transpose_w_kernel(const float* __restrict__ w) {
    int i = blockIdx.x * blockDim.x + threadIdx.x;
    if (i < NO * NC * KT) {
        int o  = i / (NC * KT);
        int cj = i % (NC * KT);
        g_wt[cj * NO + o] = w[i];
    }
}

extern __shared__ float xs[];  // [NC][XSTRIDE]

__global__ __launch_bounds__(256, 2) void taconv_kernel(
    const float* __restrict__ x, const float* __restrict__ bias,
    float* __restrict__ out, int T)
{
    const int b    = blockIdx.y;
    const int base = blockIdx.x * T_TILE;
    const int tid  = threadIdx.x;
    const int lane = tid & 31;
    const int og   = tid >> 5;   // warp id = output-channel group (8 ch each)

    // ---- cooperative load of x tile (all 64 channels, 290 t incl. halo) ----
    const float* xb = x + ((size_t)b * NC) * T;
    for (int c = 0; c < NC; ++c) {
        const float* xr = xb + (size_t)c * T;
        float* sr = xs + c * XSTRIDE;
        for (int i = tid; i < XT; i += 256) {
            int g = base - HALO + i;
            sr[i] = (g >= 0 && g < T) ? __ldg(xr + g) : 0.0f;
        }
    }
    __syncthreads();

    // ---- register tile: 8 output channels x 8 t-points (stride 32) ----
    float acc[64];
#pragma unroll
    for (int i = 0; i < 64; ++i) acc[i] = 0.0f;

    const float* wbase = g_wt + og * 8;

    for (int c = 0; c < NC; ++c) {
        const float* xr = xs + c * XSTRIDE + HALO + lane;
        const float* wc = wbase + c * (KT * NO);
#pragma unroll
        for (int j = 0; j < 9; ++j) {
            const int d = 16 * (j / 3) + (j % 3) - 17;   // compile-time constant
            float4 wa = *(const float4*)(wc + j * NO);
            float4 wb = *(const float4*)(wc + j * NO + 4);
            float w8[8] = {wa.x, wa.y, wa.z, wa.w, wb.x, wb.y, wb.z, wb.w};
#pragma unroll
            for (int k = 0; k < 8; ++k) {
                float xv = xr[d + 32 * k];
#pragma unroll
                for (int o = 0; o < 8; ++o)
                    acc[o * 8 + k] = fmaf(w8[o], xv, acc[o * 8 + k]);
            }
        }
    }

    // ---- epilogue: add bias, coalesced stores ----
    float* ob = out + ((size_t)b * NO + og * 8) * T + base + lane;
#pragma unroll
    for (int o = 0; o < 8; ++o) {
        float bv = __ldg(bias + og * 8 + o);
        float* op = ob + (size_t)o * T;
#pragma unroll
        for (int k = 0; k < 8; ++k)
            op[32 * k] = acc[o * 8 + k] + bv;
    }
}

extern "C" void kernel_launch(void* const* d_in, const int* in_sizes, int n_in,
                              void* d_out, int out_size) {
    const float* x    = (const float*)d_in[0];
    const float* w    = (const float*)d_in[1];
    const float* bias = (const float*)d_in[2];
    float* out = (float*)d_out;

    const int T = 65536;
    const int B = in_sizes[0] / (NC * T);

    transpose_w_kernel<<<(NO * NC * KT + 255) / 256, 256>>>(w);

    size_t smem = (size_t)NC * XSTRIDE * sizeof(float);   // 74,240 B
    cudaFuncSetAttribute(taconv_kernel,
                         cudaFuncAttributeMaxDynamicSharedMemorySize, (int)smem);

    dim3 grid((T + T_TILE - 1) / T_TILE, B);
    taconv_kernel<<<grid, 256, smem>>>(x, bias, out, T);
}